// round 6
// baseline (speedup 1.0000x reference)
#include <cuda_runtime.h>
#include <cuda_bf16.h>

// PoseSkeleton FK. Warp-uniform joints; rot/pos in padded float4 swizzled smem
// so the chain loop uses LDS.128 (4 per level instead of 12 scalar LDS).
// Inputs: d_in[0] rot f32 (B,24,3,3), d_in[1] pos f32 (B,24,3), d_in[2] parents (fixed SMPL).
// Output: flatten(joint_transforms (B,24,4,4)) ++ flatten(posed (B,24,3)).

#define KJ    24
#define BPB   32           // batches per block
#define NTH   (KJ * BPB)   // 768
#define RSTR  80           // rot f4 slots per batch (72 rows + xor headroom, %8==0)
#define PSTR  24           // pos f4 slots per batch (%8==0)
#define OT_F4 (KJ * 4)     // 96 f4 per batch (4x4 transforms)
#define SOP   33           // outP scalar stride

#define ROT_E (KJ * 9)     // 216 floats/batch
#define POS_E (KJ * 3)     // 72

// smem: rot f4 [32*80] + pos f4 [32*24] + outT f4 [32*96] + outP scalar [72*33]
#define SMEM_BYTES ((BPB * RSTR + BPB * PSTR + BPB * OT_F4) * 16 + POS_E * SOP * 4)
// = (2560+768+3072)*16 + 2376*4 = 102400 + 9504 = 111904 B  -> 2 CTAs/SM

struct ChainTab {
    unsigned long long pk[KJ];  // 5-bit packed root-to-self ancestor chain
    int dep[KJ];
};

__host__ __device__ constexpr ChainTab make_chains() {
    ChainTab c{};
    const int par[KJ] = {0, 0, 0, 0, 1, 2, 3, 4, 5, 6, 7, 8,
                         9, 9, 9, 12, 13, 14, 16, 17, 18, 19, 20, 21};
    for (int j = 0; j < KJ; ++j) {
        int tmp[10] = {};
        int n = 0;
        int x = j;
        while (true) { tmp[n++] = x; if (x == 0) break; x = par[x]; }
        unsigned long long pk = 0;
        for (int d = 0; d < n; ++d)
            pk |= (unsigned long long)(tmp[n - 1 - d]) << (5 * d);
        c.pk[j] = pk;
        c.dep[j] = n;
    }
    return c;
}

__constant__ ChainTab CHT = make_chains();

__global__ __launch_bounds__(NTH, 2)
void fk_kernel(const float* __restrict__ rot,
               const float* __restrict__ pos,
               float* __restrict__ outT,
               float* __restrict__ outP)
{
    extern __shared__ float4 sm4[];
    float4* rotS4  = sm4;                         // [32*80]
    float4* posS4  = rotS4 + BPB * RSTR;          // [32*24]
    float4* outTS4 = posS4 + BPB * PSTR;          // [32*96]
    float*  outPS  = reinterpret_cast<float*>(outTS4 + BPB * OT_F4);  // [72*33]
    float*  rotSf  = reinterpret_cast<float*>(rotS4);
    float*  posSf  = reinterpret_cast<float*>(posS4);

    const int    t  = threadIdx.x;
    const size_t b0 = (size_t)blockIdx.x * BPB;

    // ---- stage inputs: scalar coalesced LDG -> padded swizzled slots ----
    {
        const float* gr = rot + b0 * ROT_E;
        #pragma unroll
        for (int i = 0; i < 9; ++i) {                 // 32*216 floats
            int idx = t + i * NTH;
            int b   = idx / ROT_E;
            int e   = idx - b * ROT_E;
            int j   = e / 9;
            int k   = e - 9 * j;
            int r   = k / 3;
            int c   = k - 3 * r;
            int slot = b * RSTR + ((j * 3 + r) ^ (b & 7));
            rotSf[slot * 4 + c] = gr[idx];
        }
        const float* gp = pos + b0 * POS_E;
        #pragma unroll
        for (int i = 0; i < 3; ++i) {                 // 32*72 floats
            int idx = t + i * NTH;
            int b   = idx / POS_E;
            int e   = idx - b * POS_E;
            int j   = e / 3;
            int c   = e - 3 * j;
            int u   = j + (b & 7);
            if (u >= PSTR) u -= PSTR;
            posSf[(b * PSTR + u) * 4 + c] = gp[idx];
        }
    }
    __syncthreads();

    // ---- compute: warp = one joint j across 32 batches (lane = b) ----
    const int j  = t >> 5;
    const int b  = t & 31;
    const int bx = b & 7;
    const int rB = b * RSTR;
    const int pB = b * PSTR;

    const unsigned long long ch = CHT.pk[j];
    const int dep = CHT.dep[j];

    // d = 0: root local transform (joint 0)
    float4 r0v = rotS4[rB + (0 ^ bx)];
    float4 r1v = rotS4[rB + (1 ^ bx)];
    float4 r2v = rotS4[rB + (2 ^ bx)];
    float4 p0v = posS4[pB + bx];
    float A0 = r0v.x, A1 = r0v.y, A2 = r0v.z;
    float A3 = r1v.x, A4 = r1v.y, A5 = r1v.z;
    float A6 = r2v.x, A7 = r2v.y, A8 = r2v.z;
    float t0 = p0v.x, t1 = p0v.y, t2 = p0v.z;
    float pp0 = t0, pp1 = t1, pp2 = t2;

    for (int d = 1; d < dep; ++d) {
        const int a  = (int)((ch >> (5 * d)) & 31ull);   // warp-uniform
        const int fa = a * 3;

        int u = a + bx;
        if (u >= PSTR) u -= PSTR;
        const float4 pav = posS4[pB + u];
        const float pa0 = pav.x, pa1 = pav.y, pa2 = pav.z;
        const float r0 = pa0 - pp0, r1 = pa1 - pp1, r2 = pa2 - pp2;

        t0 += A0 * r0 + A1 * r1 + A2 * r2;
        t1 += A3 * r0 + A4 * r1 + A5 * r2;
        t2 += A6 * r0 + A7 * r1 + A8 * r2;

        const float4 Rr0 = rotS4[rB + ((fa + 0) ^ bx)];
        const float4 Rr1 = rotS4[rB + ((fa + 1) ^ bx)];
        const float4 Rr2 = rotS4[rB + ((fa + 2) ^ bx)];
        const float R0 = Rr0.x, R1 = Rr0.y, R2 = Rr0.z;
        const float R3 = Rr1.x, R4 = Rr1.y, R5 = Rr1.z;
        const float R6 = Rr2.x, R7 = Rr2.y, R8 = Rr2.z;

        const float B0 = A0 * R0 + A1 * R3 + A2 * R6;
        const float B1 = A0 * R1 + A1 * R4 + A2 * R7;
        const float B2 = A0 * R2 + A1 * R5 + A2 * R8;
        const float B3 = A3 * R0 + A4 * R3 + A5 * R6;
        const float B4 = A3 * R1 + A4 * R4 + A5 * R7;
        const float B5 = A3 * R2 + A4 * R5 + A5 * R8;
        const float B6 = A6 * R0 + A7 * R3 + A8 * R6;
        const float B7 = A6 * R1 + A7 * R4 + A8 * R7;
        const float B8 = A6 * R2 + A7 * R5 + A8 * R8;
        A0 = B0; A1 = B1; A2 = B2;
        A3 = B3; A4 = B4; A5 = B5;
        A6 = B6; A7 = B7; A8 = B8;
        pp0 = pa0; pp1 = pa1; pp2 = pa2;
    }

    // translation column of (transforms - init_bone)
    const float tp0 = t0 - (A0 * pp0 + A1 * pp1 + A2 * pp2);
    const float tp1 = t1 - (A3 * pp0 + A4 * pp1 + A5 * pp2);
    const float tp2 = t2 - (A6 * pp0 + A7 * pp1 + A8 * pp2);

    // ---- stage outT as float4 rows with rotation swizzle (STS.128) ----
    {
        float4 rows[4];
        rows[0] = make_float4(A0, A1, A2, tp0);
        rows[1] = make_float4(A3, A4, A5, tp1);
        rows[2] = make_float4(A6, A7, A8, tp2);
        rows[3] = make_float4(0.f, 0.f, 0.f, 1.f);
        #pragma unroll
        for (int r = 0; r < 4; ++r) {
            int f = j * 4 + r + b;                // <= 126
            if (f >= OT_F4) f -= OT_F4;
            outTS4[b * OT_F4 + f] = rows[r];
        }
        // posed positions: scalar transposed (conflict-free)
        float* q = outPS + (j * 3) * SOP + b;
        q[0 * SOP] = t0; q[1 * SOP] = t1; q[2 * SOP] = t2;
    }
    __syncthreads();

    // ---- flush outT: LDS.128 (de-swizzle) + STG.128 fully coalesced ----
    {
        float4* goT4 = reinterpret_cast<float4*>(outT + b0 * (KJ * 16));
        const int f0  = t % OT_F4;
        const int bbB = t / OT_F4;                 // 0..7
        #pragma unroll
        for (int i = 0; i < 4; ++i) {              // 32*96 = 3072 float4
            int bb = bbB + 8 * i;
            int f  = f0 + bb;
            if (f >= OT_F4) f -= OT_F4;
            goT4[t + i * NTH] = outTS4[bb * OT_F4 + f];
        }
        // flush posed positions: scalar transposed LDS, coalesced STG
        float* goP = outP + b0 * POS_E;
        #pragma unroll
        for (int i = 0; i < 3; ++i) {
            int g  = t + i * NTH;
            int bb = g / POS_E;
            int e  = g - bb * POS_E;
            goP[g] = outPS[e * SOP + bb];
        }
    }
}

extern "C" void kernel_launch(void* const* d_in, const int* in_sizes, int n_in,
                              void* d_out, int out_size)
{
    const float* rot = (const float*)d_in[0];
    const float* pos = (const float*)d_in[1];
    // d_in[2] = parents (int64) — fixed SMPL tree, baked into CHT.

    int nB = in_sizes[0] / (KJ * 9);   // 131072

    float* out  = (float*)d_out;
    float* outT = out;                              // (B,24,4,4)
    float* outP = out + (size_t)nB * KJ * 16;       // (B,24,3)

    static bool attr_set = false;
    if (!attr_set) {
        cudaFuncSetAttribute(fk_kernel,
                             cudaFuncAttributeMaxDynamicSharedMemorySize,
                             SMEM_BYTES);
        attr_set = true;
    }

    int blocks = nB / BPB;             // 4096
    fk_kernel<<<blocks, NTH, SMEM_BYTES>>>(rot, pos, outT, outP);
}

// round 7
// speedup vs baseline: 2.3326x; 2.3326x over previous
#include <cuda_runtime.h>
#include <cuda_bf16.h>
#include <cstdint>

// PoseSkeleton FK — thread-per-batch, minimal 23 matmuls/batch.
// 4-slot compile-time register allocation for live parent transforms.
// cp.async double-buffered input chunks; smem-staged coalesced output flush.
// Inputs: d_in[0] rot f32 (B,24,3,3), d_in[1] pos f32 (B,24,3), d_in[2] parents (fixed SMPL).
// Output: flatten(joint_transforms (B,24,4,4)) ++ flatten(posed (B,24,3)).

#define KJ    24
#define BPB   128        // batches per block = threads per block
#define NCH   6          // chunks
#define JC    4          // joints per chunk (4*9 floats = 9 float4, aligned)
#define INSTR 13         // inS stride in float4 (12 used; odd -> conflict-free)
#define OTSTR 17         // outT stride in float4 (16 used; odd -> conflict-free)

#define INS_F4  (BPB * INSTR)              // 1664
#define OTS_F4  (BPB * OTSTR)              // 2176
#define SMEM_BYTES ((2 * INS_F4 + OTS_F4) * 16)   // 88064 B -> 2 CTAs/SM

__device__ __forceinline__ void cpasync16(uint32_t dst, const float4* src) {
    asm volatile("cp.async.cg.shared.global [%0], [%1], 16;\n" :: "r"(dst), "l"(src));
}
__device__ __forceinline__ void cpasync_commit() {
    asm volatile("cp.async.commit_group;\n" ::: "memory");
}
template <int N> __device__ __forceinline__ void cpasync_wait() {
    asm volatile("cp.async.wait_group %0;\n" :: "n"(N) : "memory");
}

// Parent-slot / write-slot tables (derived from SMPL parents
// {0,0,0,0,1,2,3,4,5,6,7,8,9,9,9,12,13,14,16,17,18,19,20,21}).
// PJ[j] = slot holding parent transform when j is processed; WJ[j] = slot j
// writes (-1 = leaf, no slot needed). Verified: every PJ read sees the right
// joint; max 4 slots ever live.
__device__ __constant__ int dummy_unused;  // (keep nvcc happy if tables unused)

__global__ __launch_bounds__(BPB, 2)
void fk_kernel(const float4* __restrict__ rot4,   // [B][54]
               const float4* __restrict__ pos4,   // [B][18]
               float4* __restrict__ outT4,        // [B][96]
               float4* __restrict__ outP4)        // [B][18]
{
    extern __shared__ float4 sm4[];
    float4* inS0 = sm4;
    float4* inS1 = sm4 + INS_F4;
    float4* otS  = sm4 + 2 * INS_F4;

    const int    t  = threadIdx.x;
    const size_t b0 = (size_t)blockIdx.x * BPB;

    const uint32_t inB0 = (uint32_t)__cvta_generic_to_shared(inS0);
    const uint32_t inB1 = (uint32_t)__cvta_generic_to_shared(inS1);

    // ---- async-stage one chunk: coalesced 16B gmem -> strided smem ----
    auto issue_chunk = [&](int c, uint32_t base) {
        #pragma unroll
        for (int i = 0; i < 9; ++i) {                 // rot: 128*9 f4
            int g = t + i * BPB;
            int b = g / 9, e = g - 9 * b;
            cpasync16(base + (uint32_t)(b * INSTR + e) * 16,
                      rot4 + (b0 + b) * 54 + c * 9 + e);
        }
        #pragma unroll
        for (int i = 0; i < 3; ++i) {                 // pos: 128*3 f4
            int g = t + i * BPB;
            int b = g / 3, e = g - 3 * b;
            cpasync16(base + (uint32_t)(b * INSTR + 9 + e) * 16,
                      pos4 + (b0 + b) * 18 + c * 3 + e);
        }
        cpasync_commit();
    };

    issue_chunk(0, inB0);

    // 4-slot FK state (constant-indexed -> registers)
    float SR[4][9], ST[4][3], SP[4][3];

    constexpr int PJ[KJ] = {-1, 0, 0, 0,  1, 2, 3,  1, 2, 3,  1, 2,
                             3, 3, 3,  0,  1, 2,  1, 2,  1, 2,  1, 2};
    constexpr int WJ[KJ] = { 0, 1, 2, 3,  1, 2, 3,  1, 2, 3, -1,-1,
                             0, 1, 2, -1,  1, 2,  1, 2,  1, 2, -1,-1};

    #pragma unroll
    for (int c = 0; c < NCH; ++c) {
        if (c + 1 < NCH) {
            issue_chunk(c + 1, ((c + 1) & 1) ? inB1 : inB0);
            cpasync_wait<1>();          // chunk c landed
        } else {
            cpasync_wait<0>();
        }
        __syncthreads();

        // unpack my batch's chunk: 12 LDS.128 (conflict-free, odd stride)
        float cb[48];
        {
            const float4* ib = ((c & 1) ? inS1 : inS0) + t * INSTR;
            #pragma unroll
            for (int e = 0; e < 12; ++e) {
                float4 v = ib[e];
                cb[4 * e + 0] = v.x; cb[4 * e + 1] = v.y;
                cb[4 * e + 2] = v.z; cb[4 * e + 3] = v.w;
            }
        }

        float pd[12];   // posed positions for this chunk

        #pragma unroll
        for (int jl = 0; jl < JC; ++jl) {
            const int j = c * JC + jl;
            const float R0 = cb[jl*9+0], R1 = cb[jl*9+1], R2 = cb[jl*9+2];
            const float R3 = cb[jl*9+3], R4 = cb[jl*9+4], R5 = cb[jl*9+5];
            const float R6 = cb[jl*9+6], R7 = cb[jl*9+7], R8 = cb[jl*9+8];
            const float px = cb[36+jl*3+0], py = cb[36+jl*3+1], pz = cb[36+jl*3+2];

            float T0,T1,T2,T3,T4,T5,T6,T7,T8, tx,ty,tz;
            if (j == 0) {
                T0=R0;T1=R1;T2=R2;T3=R3;T4=R4;T5=R5;T6=R6;T7=R7;T8=R8;
                tx = px; ty = py; tz = pz;
            } else {
                const int ps = PJ[j];
                const float rx = px - SP[ps][0];
                const float ry = py - SP[ps][1];
                const float rz = pz - SP[ps][2];
                tx = SR[ps][0]*rx + SR[ps][1]*ry + SR[ps][2]*rz + ST[ps][0];
                ty = SR[ps][3]*rx + SR[ps][4]*ry + SR[ps][5]*rz + ST[ps][1];
                tz = SR[ps][6]*rx + SR[ps][7]*ry + SR[ps][8]*rz + ST[ps][2];
                T0 = SR[ps][0]*R0 + SR[ps][1]*R3 + SR[ps][2]*R6;
                T1 = SR[ps][0]*R1 + SR[ps][1]*R4 + SR[ps][2]*R7;
                T2 = SR[ps][0]*R2 + SR[ps][1]*R5 + SR[ps][2]*R8;
                T3 = SR[ps][3]*R0 + SR[ps][4]*R3 + SR[ps][5]*R6;
                T4 = SR[ps][3]*R1 + SR[ps][4]*R4 + SR[ps][5]*R7;
                T5 = SR[ps][3]*R2 + SR[ps][4]*R5 + SR[ps][5]*R8;
                T6 = SR[ps][6]*R0 + SR[ps][7]*R3 + SR[ps][8]*R6;
                T7 = SR[ps][6]*R1 + SR[ps][7]*R4 + SR[ps][8]*R7;
                T8 = SR[ps][6]*R2 + SR[ps][7]*R5 + SR[ps][8]*R8;
            }
            if (WJ[j] >= 0) {
                const int w = (WJ[j] >= 0) ? WJ[j] : 0;
                SR[w][0]=T0; SR[w][1]=T1; SR[w][2]=T2;
                SR[w][3]=T3; SR[w][4]=T4; SR[w][5]=T5;
                SR[w][6]=T6; SR[w][7]=T7; SR[w][8]=T8;
                ST[w][0]=tx; ST[w][1]=ty; ST[w][2]=tz;
                SP[w][0]=px; SP[w][1]=py; SP[w][2]=pz;
            }

            // translation column of (transforms - init_bone)
            const float ox = tx - (T0*px + T1*py + T2*pz);
            const float oy = ty - (T3*px + T4*py + T5*pz);
            const float oz = tz - (T6*px + T7*py + T8*pz);

            float4* od = otS + t * OTSTR + jl * 4;    // conflict-free STS.128
            od[0] = make_float4(T0, T1, T2, ox);
            od[1] = make_float4(T3, T4, T5, oy);
            od[2] = make_float4(T6, T7, T8, oz);
            od[3] = make_float4(0.f, 0.f, 0.f, 1.f);

            pd[jl*3+0] = tx; pd[jl*3+1] = ty; pd[jl*3+2] = tz;
        }

        // posed positions: direct STG.128 x3 (48B/batch/chunk; L2 merges)
        {
            float4* pq = outP4 + (b0 + t) * 18 + c * 3;
            pq[0] = make_float4(pd[0], pd[1], pd[2],  pd[3]);
            pq[1] = make_float4(pd[4], pd[5], pd[6],  pd[7]);
            pq[2] = make_float4(pd[8], pd[9], pd[10], pd[11]);
        }
        __syncthreads();

        // flush outT chunk: conflict-free LDS.128, fully coalesced STG.128
        #pragma unroll
        for (int i = 0; i < 16; ++i) {                 // 128*16 f4
            int g  = t + i * BPB;
            int bb = g >> 4;
            int r  = g & 15;
            outT4[(b0 + bb) * 96 + c * 16 + r] = otS[bb * OTSTR + r];
        }
        __syncthreads();   // otS + inS[c&1] safe to reuse
    }
}

extern "C" void kernel_launch(void* const* d_in, const int* in_sizes, int n_in,
                              void* d_out, int out_size)
{
    const float4* rot4 = (const float4*)d_in[0];
    const float4* pos4 = (const float4*)d_in[1];
    // d_in[2] = parents (int64) — fixed SMPL tree, baked into PJ/WJ tables.

    int nB = in_sizes[0] / (KJ * 9);   // 131072

    float*  out   = (float*)d_out;
    float4* outT4 = (float4*)out;                               // (B,24,4,4)
    float4* outP4 = (float4*)(out + (size_t)nB * KJ * 16);      // (B,24,3)

    static bool attr_set = false;
    if (!attr_set) {
        cudaFuncSetAttribute(fk_kernel,
                             cudaFuncAttributeMaxDynamicSharedMemorySize,
                             SMEM_BYTES);
        attr_set = true;
    }

    int blocks = nB / BPB;             // 1024
    fk_kernel<<<blocks, BPB, SMEM_BYTES>>>(rot4, pos4, outT4, outP4);
}